// round 17
// baseline (speedup 1.0000x reference)
#include <cuda_runtime.h>
#include <math.h>

// out[row] = tanh(sqrt(sum_j (w[row][j] - x[j])^2)), row in [0, 1048576), j in [0, 256)
//
// Champion structure (2 rows/warp, evict-first streaming weight reads,
// warp-shuffle reduce, hardware tanh.approx) upgraded to Blackwell 256-bit
// global loads (ld.global.nc.cs.v8.f32 -> LDG.E.256): lane l covers floats
// [8l, 8l+8) of each 1KB row, so a row is ONE warp load (1024B) instead of
// two. Same addresses/sectors as champion; half the L1tex wavefronts and LSU
// slots per byte.

__device__ __forceinline__ float htanh(float v) {
    float r;
    asm("tanh.approx.f32 %0, %1;" : "=f"(r) : "f"(v));
    return r;
}

// 256-bit streaming (evict-first) non-coherent global load, sm_100+.
__device__ __forceinline__ void ldg256_cs(const float* p, float4& lo, float4& hi) {
    asm volatile(
        "ld.global.nc.cs.v8.f32 {%0,%1,%2,%3,%4,%5,%6,%7}, [%8];"
        : "=f"(lo.x), "=f"(lo.y), "=f"(lo.z), "=f"(lo.w),
          "=f"(hi.x), "=f"(hi.y), "=f"(hi.z), "=f"(hi.w)
        : "l"(p));
}

__global__ __launch_bounds__(256) void sonia_l2_tanh_kernel256(
    const float* __restrict__ x,
    const float* __restrict__ w,
    float* __restrict__ out,
    int n_rows)
{
    const int warp_id = (blockIdx.x * blockDim.x + threadIdx.x) >> 5;
    const int lane    = threadIdx.x & 31;
    const int row0    = warp_id * 2;
    if (row0 >= n_rows) return;

    // Lane l handles columns [8l, 8l+8) of each row.
    const float* __restrict__ wr = w + (size_t)row0 * 256 + lane * 8;

    // Two independent 256-bit streaming loads: one full 1KB row each.
    float4 a0, a1, b0, b1;
    ldg256_cs(wr,       a0, a1);
    ldg256_cs(wr + 256, b0, b1);

    // x is tiny and re-read by every warp: L1/L2 resident (two 128-bit loads).
    const float4* __restrict__ xr = reinterpret_cast<const float4*>(x + lane * 8);
    const float4 x0 = __ldg(xr);
    const float4 x1 = __ldg(xr + 1);

    float d;
    float sa = 0.0f, sb = 0.0f;
    d = a0.x - x0.x; sa = fmaf(d, d, sa);
    d = a0.y - x0.y; sa = fmaf(d, d, sa);
    d = a0.z - x0.z; sa = fmaf(d, d, sa);
    d = a0.w - x0.w; sa = fmaf(d, d, sa);
    d = a1.x - x1.x; sa = fmaf(d, d, sa);
    d = a1.y - x1.y; sa = fmaf(d, d, sa);
    d = a1.z - x1.z; sa = fmaf(d, d, sa);
    d = a1.w - x1.w; sa = fmaf(d, d, sa);

    d = b0.x - x0.x; sb = fmaf(d, d, sb);
    d = b0.y - x0.y; sb = fmaf(d, d, sb);
    d = b0.z - x0.z; sb = fmaf(d, d, sb);
    d = b0.w - x0.w; sb = fmaf(d, d, sb);
    d = b1.x - x1.x; sb = fmaf(d, d, sb);
    d = b1.y - x1.y; sb = fmaf(d, d, sb);
    d = b1.z - x1.z; sb = fmaf(d, d, sb);
    d = b1.w - x1.w; sb = fmaf(d, d, sb);

    // Butterfly reduce both sums across the warp.
    #pragma unroll
    for (int off = 16; off > 0; off >>= 1) {
        sa += __shfl_xor_sync(0xFFFFFFFFu, sa, off);
        sb += __shfl_xor_sync(0xFFFFFFFFu, sb, off);
    }

    if (lane == 0) {
        out[row0]     = htanh(sqrtf(sa));
        if (row0 + 1 < n_rows)
            out[row0 + 1] = htanh(sqrtf(sb));
    }
}

extern "C" void kernel_launch(void* const* d_in, const int* in_sizes, int n_in,
                              void* d_out, int out_size)
{
    const float* x = (const float*)d_in[0];   // input  [1, 256]
    const float* w = (const float*)d_in[1];   // weight [out_size, 256]
    float* out     = (float*)d_out;

    const int n_rows = out_size;              // 1048576
    // 8 warps/block, 2 rows/warp -> 16 rows per block
    const int rows_per_block = 16;
    const int blocks = (n_rows + rows_per_block - 1) / rows_per_block;

    sonia_l2_tanh_kernel256<<<blocks, 256>>>(x, w, out, n_rows);
}